// round 16
// baseline (speedup 1.0000x reference)
#include <cuda_runtime.h>
#include <cstdint>

// AF2dMADEBlock: wavefront-parallel raster sweep (t = x + 2y, 22 steps).
// R16: TWO BATCHES PER CLUSTER. Weight registers (80/thread, the RF-limiting
// resource) are shared across batches; the second batch's work interleaves
// into the dependency-stall holes of the first (kernel was latency-bound at
// 28% issue). Per-thread dot partials live in smem (1 float each, hsum'd).
// 16 clusters x 2 CTAs (rank0=mu, rank1=lv), 512 thr/CTA, dynamic smem.

#define EPS 1e-12f
#define H1OFF (67*64)        // layer-1 offset within a batch's hg (floats)
#define HGB   (2*67*64)      // per-batch hg size (floats)
typedef unsigned long long ull;

__device__ __forceinline__ uint32_t smem_u32(const void* p){
  return (uint32_t)__cvta_generic_to_shared((void*)p);
}
__device__ __forceinline__ float elu_f(float x){
  return x > 0.f ? x : (__expf(x) - 1.f);
}
__device__ __forceinline__ void fma2(ull& acc, ull a, ull b){
  asm("fma.rn.f32x2 %0, %1, %2, %0;" : "+l"(acc) : "l"(a), "l"(b));
}
__device__ __forceinline__ ull pack2(float lo, float hi){
  ull r; asm("mov.b64 %0, {%1, %2};" : "=l"(r) : "f"(lo), "f"(hi)); return r;
}
__device__ __forceinline__ float hsum1(ull a){
  float x, y;
  asm("mov.b64 {%0, %1}, %2;" : "=f"(x), "=f"(y) : "l"(a));
  return x + y;
}
__device__ __forceinline__ void wf(int w, int& ymin, int& n){
  ymin = (w <= 7) ? 0 : ((w - 6) >> 1);
  int ymax = w >> 1; if (ymax > 7) ymax = 7;
  n = ymax - ymin + 1;
  if (n < 0) n = 0;
}

__global__ void __cluster_dims__(2,1,1) __launch_bounds__(512,1)
made_flow_kernel(const float* __restrict__ xg,
  const float* __restrict__ mw0, const float* __restrict__ mb0,
  const float* __restrict__ mw1, const float* __restrict__ mb1,
  const float* __restrict__ mw2, const float* __restrict__ mb2,
  const float* __restrict__ mwo, const float* __restrict__ mbo,
  const float* __restrict__ lw0, const float* __restrict__ lb0,
  const float* __restrict__ lw1, const float* __restrict__ lb1,
  const float* __restrict__ lw2, const float* __restrict__ lb2,
  const float* __restrict__ lwo, const float* __restrict__ lbo,
  float* __restrict__ out, int out_n)
{
  // dynamic smem: hg[2 batches][2 layers][67 rows][64] + partials
  extern __shared__ __align__(16) float dsm[];
  float* hg0    = dsm;                 // 2*HGB floats
  float* partsA = dsm + 2*HGB;         // [2][4][512]
  float* partsB = partsA + 4096;       // [2][4][512]

  __shared__ __align__(16) float w0s[16*64];    // mask-A w0: [(tap*4+ic)][o]
  __shared__ __align__(16) float y_s[2][65*4];  // row 64 = zero
  __shared__ __align__(16) float x_s[2][256];
  __shared__ __align__(16) float h2s[2][4*68];  // [b][slot*68+ch]
  __shared__ float b0s[64], b1s[64], b2s[64];
  __shared__ __align__(16) float wos[4*68];     // [oc][c], stride 68
  __shared__ float bos[4];
  __shared__ __align__(16) float recv[2][2][2][16]; // [par][b][net][slot*4+oc]
  __shared__ float ls32[32];
  __shared__ __align__(8) unsigned long long mbar[2];
  __shared__ uchar4 pixT[23];
  __shared__ uchar4 tapT[23][4];
  __shared__ unsigned char nT[24];

  const int tid = threadIdx.x;
  uint32_t rank; asm("mov.u32 %0, %%cluster_ctarank;" : "=r"(rank));
  const int cid = blockIdx.x >> 1;     // cluster id: batches 2cid, 2cid+1

  const float* w0g = rank ? lw0 : mw0;
  const float* b0g = rank ? lb0 : mb0;
  const float* w1g = rank ? lw1 : mw1;
  const float* b1g = rank ? lb1 : mb1;
  const float* w2g = rank ? lw2 : mw2;
  const float* b2g = rank ? lb2 : mb2;
  const float* wog = rank ? lwo : mwo;
  const float* bog = rank ? lbo : mbo;

  if (tid == 0){
    asm volatile("mbarrier.init.shared.b64 [%0], %1;"
                 :: "r"(smem_u32(&mbar[0])), "r"(1u) : "memory");
    asm volatile("mbarrier.init.shared.b64 [%0], %1;"
                 :: "r"(smem_u32(&mbar[1])), "r"(1u) : "memory");
    // arm both parities: t=0,1 have n=1 -> 2 batches * 8 floats = 64B
    asm volatile("mbarrier.arrive.expect_tx.shared.b64 _, [%0], %1;"
                 :: "r"(smem_u32(&mbar[0])), "r"(64u) : "memory");
    asm volatile("mbarrier.arrive.expect_tx.shared.b64 _, [%0], %1;"
                 :: "r"(smem_u32(&mbar[1])), "r"(64u) : "memory");
  }

  // ---- Wavefront tables ----
  if (tid < 92){
    int w = tid >> 2, k = tid & 3;
    int ymin, n; wf(w, ymin, n);
    if (k == 0) nT[w] = (unsigned char)n;
    unsigned char pix = 65, tq[4] = {64,64,64,64};
    if (k < n){
      int y = ymin + k, x = w - 2*y;
      pix = (unsigned char)(y*8 + x);
      #pragma unroll
      for (int tt = 0; tt < 3; tt++){
        int qy = y - 1, qx = x - 1 + tt;
        tq[tt] = (qy >= 0 && qx >= 0 && qx < 8) ? (unsigned char)(qy*8 + qx) : 64;
      }
      tq[3] = (x > 0) ? (unsigned char)(pix - 1) : 64;
    }
    ((unsigned char*)&pixT[w])[k] = pix;
    tapT[w][k] = make_uchar4(tq[0], tq[1], tq[2], tq[3]);
  }
  if (tid == 92) nT[23] = 0;

  // ---- Stage small weights/biases/x; zero rows & partials ----
  for (int idx = tid; idx < 1024; idx += 512){
    int r = idx >> 6, oo = idx & 63;
    int t = r >> 2, ic = r & 3;
    int ky = (t == 3) ? 1 : 0;
    int kx = (t == 3) ? 0 : t;
    w0s[idx] = w0g[(oo*4 + ic)*9 + ky*3 + kx];
  }
  if (tid < 64){
    float bv = b0g[tid];
    b0s[tid] = bv; b1s[tid] = b1g[tid]; b2s[tid] = b2g[tid];
    float e = elu_f(bv);
    #pragma unroll
    for (int b = 0; b < 2; b++){
      hg0[b*HGB + tid] = e;                   // h0[pixel 0]
      hg0[b*HGB + 64*64 + tid] = 0.f;         // zero rows
      hg0[b*HGB + H1OFF + 64*64 + tid] = 0.f;
    }
  }
  if (tid < 256) wos[(tid >> 6)*68 + (tid & 63)] = wog[tid];
  if (tid < 4){  bos[tid] = bog[tid]; y_s[0][256 + tid] = 0.f; y_s[1][256 + tid] = 0.f; }
  if (tid < 32)  ls32[tid] = 0.f;
  {
    int i = tid & 255, b = tid >> 8;
    x_s[b][((i & 63) << 2) + (i >> 6)] = xg[(2*cid + b)*256 + i];
  }
  #pragma unroll
  for (int z = 0; z < 8; z++){
    partsA[z*512 + tid] = 0.f;
    partsB[z*512 + tid] = 0.f;
  }

  // ---- Masked mask-B weights, packed f32x2 (shared by both batches) ----
  const int o = tid >> 3;
  const int j = tid & 7;
  ull w1p[20], w2p[20];
  #pragma unroll
  for (int i = 0; i < 10; i++){
    float t1[4], t2[4];
    #pragma unroll
    for (int m = 0; m < 4; m++){
      int k  = (j << 2) + (i << 5) + m;
      int t  = k >> 6, ic = k & 63;
      int ky = (t >= 3) ? 1 : 0;
      int kx = (t >= 3) ? (t - 3) : t;
      int gi = (o*64 + ic)*9 + ky*3 + kx;
      t1[m] = w1g[gi];
      t2[m] = w2g[gi];
    }
    w1p[2*i]   = pack2(t1[0], t1[1]);
    w1p[2*i+1] = pack2(t1[2], t1[3]);
    w2p[2*i]   = pack2(t2[0], t2[1]);
    w2p[2*i+1] = pack2(t2[2], t2[3]);
  }

  __syncthreads();
  asm volatile("barrier.cluster.arrive.aligned;" ::: "memory");
  asm volatile("barrier.cluster.wait.aligned;"   ::: "memory");

  float lsacc = 0.f;
  float h0up[2] = {0.f, 0.f};          // per-thread hoisted h0 partial
  const int joff = j << 2;
  const int wid = tid >> 5;

  for (int t = 0; t < 22; t++){
    const int n  = nT[t];
    const int n1 = nT[t+1];
    const uchar4 pxv = pixT[t];
    const int pls[4] = {pxv.x, pxv.y, pxv.z, pxv.w};

    // ---- Phase A: h1 for wave-t pixels, both batches ----
    {
      float s[2][4];
      #pragma unroll
      for (int b = 0; b < 2; b++){
        const float* hb = hg0 + b*HGB;
        #pragma unroll
        for (int k = 0; k < 4; k++){
          if (k < n){
            const float* cb = &hb[pls[k]*64 + joff];
            ulonglong2 c0 = *(const ulonglong2*)cb;
            ulonglong2 c1 = *(const ulonglong2*)(cb + 32);
            ull a = 0ull;
            fma2(a, w1p[16], c0.x); fma2(a, w1p[17], c0.y);
            fma2(a, w1p[18], c1.x); fma2(a, w1p[19], c1.y);
            s[b][k] = partsA[(b*4 + k)*512 + tid] + hsum1(a);
          } else s[b][k] = 0.f;
        }
      }
      #pragma unroll
      for (int r = 4; r >= 1; r >>= 1){
        #pragma unroll
        for (int b = 0; b < 2; b++)
          #pragma unroll
          for (int k = 0; k < 4; k++)
            s[b][k] += __shfl_xor_sync(0xffffffffu, s[b][k], r, 8);
      }
      if (j == 0){
        #pragma unroll
        for (int b = 0; b < 2; b++)
          #pragma unroll
          for (int k = 0; k < 4; k++)
            if (k < n) hg0[b*HGB + H1OFF + pls[k]*64 + o] = elu_f(b1s[o] + s[b][k]);
      }
    }
    __syncthreads();

    // ---- Phase B: h2 for wave-t pixels, both batches ----
    {
      float s[2][4];
      #pragma unroll
      for (int b = 0; b < 2; b++){
        const float* hb = hg0 + b*HGB + H1OFF;
        #pragma unroll
        for (int k = 0; k < 4; k++){
          if (k < n){
            const float* cb = &hb[pls[k]*64 + joff];
            ulonglong2 c0 = *(const ulonglong2*)cb;
            ulonglong2 c1 = *(const ulonglong2*)(cb + 32);
            ull a = 0ull;
            fma2(a, w2p[16], c0.x); fma2(a, w2p[17], c0.y);
            fma2(a, w2p[18], c1.x); fma2(a, w2p[19], c1.y);
            s[b][k] = partsB[(b*4 + k)*512 + tid] + hsum1(a);
          } else s[b][k] = 0.f;
        }
      }
      #pragma unroll
      for (int r = 4; r >= 1; r >>= 1){
        #pragma unroll
        for (int b = 0; b < 2; b++)
          #pragma unroll
          for (int k = 0; k < 4; k++)
            s[b][k] += __shfl_xor_sync(0xffffffffu, s[b][k], r, 8);
      }
      if (j == 0){
        #pragma unroll
        for (int b = 0; b < 2; b++)
          #pragma unroll
          for (int k = 0; k < 4; k++)
            if (k < n) h2s[b][k*68 + o] = elu_f(b2s[o] + s[b][k]);
      }
    }
    __syncthreads();

    // ---- Phase C ----
    const int par = t & 1;
    const uint32_t parity = (uint32_t)((t >> 1) & 1);

    // conv + send: warps 4-7 -> batch 0, warps 8-11 -> batch 1
    if (wid >= 4 && wid < 12){
      const int cb = (wid >= 8);
      const int kp = wid - 4 - cb*4;
      const int oc = (tid >> 3) & 3;
      const int j8 = tid & 7;
      if (kp < n){
        const ulonglong2* hp = (const ulonglong2*)&h2s[cb][kp*68 + j8*8];
        const ulonglong2* wp = (const ulonglong2*)&wos[oc*68 + j8*8];
        ulonglong2 hv0 = hp[0], hv1 = hp[1];
        ulonglong2 wv0 = wp[0], wv1 = wp[1];
        ull a0 = 0ull, a1 = 0ull;
        fma2(a0, wv0.x, hv0.x); fma2(a1, wv0.y, hv0.y);
        fma2(a0, wv1.x, hv1.x); fma2(a1, wv1.y, hv1.y);
        float pr = hsum1(a0) + hsum1(a1);
        pr += __shfl_xor_sync(0xffffffffu, pr, 4, 8);
        pr += __shfl_xor_sync(0xffffffffu, pr, 2, 8);
        pr += __shfl_xor_sync(0xffffffffu, pr, 1, 8);
        if (j8 == 0){
          float v = bos[oc] + pr;
          if (rank){ v *= 0.5f; lsacc += v; }
          uint32_t val = __float_as_uint(v);
          uint32_t lrec = smem_u32(&recv[par][cb][rank][(kp << 2) + oc]);
          uint32_t lbar = smem_u32(&mbar[par]);
          uint32_t d0, b0a, d1, b1a;
          asm volatile("mapa.shared::cluster.u32 %0, %1, %2;" : "=r"(d0)  : "r"(lrec), "r"(0u));
          asm volatile("mapa.shared::cluster.u32 %0, %1, %2;" : "=r"(b0a) : "r"(lbar), "r"(0u));
          asm volatile("mapa.shared::cluster.u32 %0, %1, %2;" : "=r"(d1)  : "r"(lrec), "r"(1u));
          asm volatile("mapa.shared::cluster.u32 %0, %1, %2;" : "=r"(b1a) : "r"(lbar), "r"(1u));
          asm volatile("st.async.shared::cluster.mbarrier::complete_tx::bytes.u32 [%0], %1, [%2];"
                       :: "r"(d0), "r"(val), "r"(b0a) : "memory");
          asm volatile("st.async.shared::cluster.mbarrier::complete_tx::bytes.u32 [%0], %1, [%2];"
                       :: "r"(d1), "r"(val), "r"(b1a) : "memory");
        }
      }
    }

    // past-tap partials for wave t+1, both layers, both batches -> smem
    #pragma unroll
    for (int b = 0; b < 2; b++){
      const float* hb = hg0 + b*HGB;
      #pragma unroll
      for (int k = 0; k < 4; k++){
        if (k < n1){
          const uchar4 tq = tapT[t+1][k];
          const int taps[4] = {tq.x, tq.y, tq.z, tq.w};
          ull A = 0ull, B = 0ull;
          #pragma unroll
          for (int m = 0; m < 4; m++){
            const float* bp = &hb[taps[m]*64 + joff];
            ulonglong2 u0 = *(const ulonglong2*)bp;
            ulonglong2 u1 = *(const ulonglong2*)(bp + 32);
            ulonglong2 v0 = *(const ulonglong2*)(bp + H1OFF);
            ulonglong2 v1 = *(const ulonglong2*)(bp + H1OFF + 32);
            fma2(A, w1p[4*m],   u0.x); fma2(A, w1p[4*m+1], u0.y);
            fma2(A, w1p[4*m+2], u1.x); fma2(A, w1p[4*m+3], u1.y);
            fma2(B, w2p[4*m],   v0.x); fma2(B, w2p[4*m+1], v0.y);
            fma2(B, w2p[4*m+2], v1.x); fma2(B, w2p[4*m+3], v1.y);
          }
          partsA[(b*4 + k)*512 + tid] = hsum1(A);
          partsB[(b*4 + k)*512 + tid] = hsum1(B);
        }
      }
    }

    // h0 partial for wave t+1: taps 0 (wave t-2) and 1 (wave t-1) are final
    {
      const int hb = tid >> 8;           // batch for h0 duty
      const int idx = tid & 255;
      const int kp = idx >> 6, ch = idx & 63;
      const uchar4 tq = tapT[t+1][kp];
      float acc = b0s[ch];
      float4 yq0 = *(const float4*)&y_s[hb][tq.x << 2];
      float4 yq1 = *(const float4*)&y_s[hb][tq.y << 2];
      acc = fmaf(w0s[0*64 + ch], yq0.x, acc);
      acc = fmaf(w0s[1*64 + ch], yq0.y, acc);
      acc = fmaf(w0s[2*64 + ch], yq0.z, acc);
      acc = fmaf(w0s[3*64 + ch], yq0.w, acc);
      acc = fmaf(w0s[4*64 + ch], yq1.x, acc);
      acc = fmaf(w0s[5*64 + ch], yq1.y, acc);
      acc = fmaf(w0s[6*64 + ch], yq1.z, acc);
      acc = fmaf(w0s[7*64 + ch], yq1.w, acc);
      h0up[0] = acc;
    }

    // SINGLE-WAITER: warp 0 polls; lanes 0-15 batch0 y, lanes 16-31 batch1 y
    if (tid < 32){
      uint32_t lbar = smem_u32(&mbar[par]);
      uint32_t done;
      do {
        asm volatile("{\n\t.reg .pred p;\n\t"
          "mbarrier.try_wait.parity.acquire.cta.shared::cta.b64 p, [%1], %2, 0x989680;\n\t"
          "selp.b32 %0, 1, 0, p;\n\t}"
          : "=r"(done) : "r"(lbar), "r"(parity) : "memory");
      } while (!done);
      if (tid == 0 && t + 2 < 22){
        asm volatile("mbarrier.arrive.expect_tx.shared.b64 _, [%0], %1;"
                     :: "r"(lbar), "r"((uint32_t)(64*nT[t+2])) : "memory");
      }
      const int yb = tid >> 4;
      const int l  = tid & 15;
      const int kp = l >> 2, c = l & 3;
      if (kp < n){
        const int p = pls[kp];
        float mu = recv[par][yb][0][(kp << 2) + c];
        float lv = recv[par][yb][1][(kp << 2) + c];
        y_s[yb][(p << 2) + c] = __fdividef(x_s[yb][(p << 2) + c] - mu, __expf(lv) + EPS);
      }
    }
    __syncthreads();

    // h0 tail: taps 2,3 (wave t) + ELU + store; tid<256 batch0, else batch1
    {
      const int hb = tid >> 8;
      const int idx = tid & 255;
      const int kp = idx >> 6, ch = idx & 63;
      const uchar4 tq = tapT[t+1][kp];
      const int wp = ((const unsigned char*)&pixT[t+1])[kp];
      float acc = h0up[0];
      float4 y2 = *(const float4*)&y_s[hb][tq.z << 2];
      float4 y3 = *(const float4*)&y_s[hb][tq.w << 2];
      acc = fmaf(w0s[ 8*64 + ch], y2.x, acc);
      acc = fmaf(w0s[ 9*64 + ch], y2.y, acc);
      acc = fmaf(w0s[10*64 + ch], y2.z, acc);
      acc = fmaf(w0s[11*64 + ch], y2.w, acc);
      acc = fmaf(w0s[12*64 + ch], y3.x, acc);
      acc = fmaf(w0s[13*64 + ch], y3.y, acc);
      acc = fmaf(w0s[14*64 + ch], y3.z, acc);
      acc = fmaf(w0s[15*64 + ch], y3.w, acc);
      hg0[hb*HGB + wp*64 + ch] = elu_f(acc);
    }
    __syncthreads();
  }

  // ---- Outputs ----
  if (rank == 0){
    const int b = tid >> 8, i = tid & 255;
    out[(2*cid + b)*256 + i] = y_s[b][((i & 63) << 2) + (i >> 6)];
  } else {
    if (wid >= 4 && wid < 12 && (tid & 7) == 0)
      ls32[(wid - 4)*4 + ((tid >> 3) & 3)] = lsacc;
    __syncthreads();
    if (tid == 0 && out_n >= 8224){
      float s0 = 0.f, s1 = 0.f;
      #pragma unroll
      for (int w = 0; w < 16; w++){ s0 += ls32[w]; s1 += ls32[16 + w]; }
      out[8192 + 2*cid]     = s0;
      out[8192 + 2*cid + 1] = s1;
    }
  }

  asm volatile("barrier.cluster.arrive.aligned;" ::: "memory");
  asm volatile("barrier.cluster.wait.aligned;"   ::: "memory");
}

extern "C" void kernel_launch(void* const* d_in, const int* in_sizes, int n_in,
                              void* d_out, int out_size) {
  const float* p[17];
  for (int i = 0; i < 17 && i < n_in; i++) p[i] = (const float*)d_in[i];
  const int dyn = (2*HGB + 2*4096) * (int)sizeof(float);  // 101,376 B
  cudaFuncSetAttribute(made_flow_kernel,
                       cudaFuncAttributeMaxDynamicSharedMemorySize, dyn);
  made_flow_kernel<<<32, 512, dyn>>>(
    p[0],
    p[1], p[2], p[3], p[4], p[5], p[6], p[7], p[8],
    p[9], p[10], p[11], p[12], p[13], p[14], p[15], p[16],
    (float*)d_out, out_size);
}